// round 4
// baseline (speedup 1.0000x reference)
#include <cuda_runtime.h>
#include <cuda_bf16.h>
#include <math.h>
#include <stdint.h>

#define BATCH 4
#define HW    512
#define CMID  64

// ---------------------------------------------------------------------------
// Scratch (allocation-free rule: __device__ globals)
// ---------------------------------------------------------------------------
__device__ __align__(256) float g_bufA[(size_t)BATCH * HW * HW * CMID];
__device__ __align__(256) float g_bufB[(size_t)BATCH * HW * HW * CMID];
__device__ __align__(256) float g_bufC[(size_t)BATCH * HW * HW * CMID];
__device__ int g_cls[BATCH];

__device__ __forceinline__ uint32_t smem_u32(const void* p) {
    uint32_t a;
    asm("{ .reg .u64 t; cvta.to.shared.u64 t, %1; cvt.u32.u64 %0, t; }"
        : "=r"(a) : "l"(p));
    return a;
}

// ldmatrix x4: A fragment (16x16 bf16, row-major). lane -> row lane%16, khalf lane/16.
__device__ __forceinline__ void ldmA(uint32_t* r, uint32_t addr) {
    asm volatile("ldmatrix.sync.aligned.m8n8.x4.shared.b16 {%0,%1,%2,%3}, [%4];"
                 : "=r"(r[0]), "=r"(r[1]), "=r"(r[2]), "=r"(r[3]) : "r"(addr));
}

// mma m16n8k16 row.col f32.bf16.bf16.f32, D += A*B
__device__ __forceinline__ void mma16816(float* d, const uint32_t* a, const uint32_t* b) {
    asm volatile(
        "mma.sync.aligned.m16n8k16.row.col.f32.bf16.bf16.f32 "
        "{%0,%1,%2,%3}, {%4,%5,%6,%7}, {%8,%9}, {%0,%1,%2,%3};"
        : "+f"(d[0]), "+f"(d[1]), "+f"(d[2]), "+f"(d[3])
        : "r"(a[0]), "r"(a[1]), "r"(a[2]), "r"(a[3]), "r"(b[0]), "r"(b[1]));
}

// ---------------------------------------------------------------------------
// 3x3 SAME conv, CIN -> 64, ReLU, via mma.sync bf16x3 implicit GEMM.
// Block: M = 128 consecutive pixels of one image row, N = 64 out channels.
// 8 warps = 4(M) x 2(N); warp tile 32x32 via 2x4 m16n8k16 fragments.
// A staged per tap (fp32 -> bf16 hi/lo, padded rows); B (weights) staged
// once, transposed to [co][ci] (col-major KxN) with hi/lo split.
// ---------------------------------------------------------------------------
template <int CIN>
__global__ void __launch_bounds__(256, 1)
conv3x3_hmma(const float* __restrict__ in, const float* __restrict__ w,
             const float* __restrict__ bias, float* __restrict__ out)
{
    constexpr int SA  = CIN + 8;     // padded row length in bf16 elems
    constexpr int SAB = SA * 2;      // bytes (16B-multiple: CIN%8==0)
    constexpr int KSTEPS = CIN / 16;
    constexpr int FH = CIN / 2;      // fp32 elems staged per thread

    extern __shared__ char sm[];
    float* bias_s = (float*)sm;                    // 64 floats
    char*  Ah = sm + 256;                          // 128 * SAB
    char*  Al = Ah + 128 * SAB;                    // 128 * SAB
    char*  Bw = Al + 128 * SAB;                    // 18 * 64 * SAB

    const int tid  = threadIdx.x;
    const int lane = tid & 31;
    const int wid  = tid >> 5;
    const int wm   = wid >> 1;      // 0..3 : M offset wm*32
    const int wn   = wid & 1;       // 0..1 : N offset wn*32
    const int x0   = blockIdx.x * 128;
    const int y    = blockIdx.y;
    const int bz   = blockIdx.z;

    if (tid < 64) bias_s[tid] = bias[tid];

    // --- stage all 9 taps of weights, transposed + hi/lo split
    // HWIO: w[(tap*CIN+ci)*64 + co]  ->  B[tap][split][co][ci]
    for (int i = tid; i < 9 * CIN * 16; i += 256) {
        int co4 = i & 15;
        int ci  = (i >> 4) % CIN;
        int tap = (i >> 4) / CIN;
        float4 v = *(const float4*)&w[((size_t)(tap * CIN + ci)) * 64 + co4 * 4];
        const float* vf = &v.x;
        char* b0 = Bw + (tap * 2 + 0) * 64 * SAB + ci * 2;
        char* b1 = Bw + (tap * 2 + 1) * 64 * SAB + ci * 2;
#pragma unroll
        for (int j = 0; j < 4; ++j) {
            int co = co4 * 4 + j;
            float f = vf[j];
            __nv_bfloat16 h = __float2bfloat16(f);
            __nv_bfloat16 l = __float2bfloat16(f - __bfloat162float(h));
            *(__nv_bfloat16*)(b0 + co * SAB) = h;
            *(__nv_bfloat16*)(b1 + co * SAB) = l;
        }
    }

    // --- A staging state
    const int px  = tid >> 1;             // pixel 0..127 (GEMM row m)
    const int ci0 = (tid & 1) * FH;       // ci chunk base
    float vv[FH];

    auto load_tap = [&](int t) {
        const int ky = t / 3, kx = t % 3;
        const int gy = y + ky - 1;
        const int gx = x0 + px + kx - 1;
        if ((unsigned)gy < HW && (unsigned)gx < HW) {
            const float* src = in + (((size_t)bz * HW + gy) * HW + gx) * CIN + ci0;
#pragma unroll
            for (int j = 0; j < FH / 4; ++j)
                *(float4*)&vv[j * 4] = *(const float4*)&src[j * 4];
        } else {
#pragma unroll
            for (int j = 0; j < FH; ++j) vv[j] = 0.f;
        }
    };

    float acc[2][4][4];
#pragma unroll
    for (int mf = 0; mf < 2; ++mf)
#pragma unroll
        for (int nf = 0; nf < 4; ++nf)
#pragma unroll
            for (int q = 0; q < 4; ++q) acc[mf][nf][q] = 0.f;

    const uint32_t AhU = smem_u32(Ah);
    const uint32_t AlU = smem_u32(Al);

    load_tap(0);

    for (int t = 0; t < 9; ++t) {
        __syncthreads();   // A smem free (previous tap's consumers done)

        // convert + store this tap's A tile (hi/lo), 16B chunks
#pragma unroll
        for (int j = 0; j < FH / 8; ++j) {
            uint32_t hp[4], lp[4];
#pragma unroll
            for (int q = 0; q < 4; ++q) {
                float f0 = vv[j * 8 + q * 2], f1 = vv[j * 8 + q * 2 + 1];
                __nv_bfloat162 h2 = __float22bfloat162_rn(make_float2(f0, f1));
                float r0 = f0 - __bfloat162float(h2.x);
                float r1 = f1 - __bfloat162float(h2.y);
                __nv_bfloat162 l2 = __float22bfloat162_rn(make_float2(r0, r1));
                hp[q] = *(uint32_t*)&h2;
                lp[q] = *(uint32_t*)&l2;
            }
            uint32_t off = (uint32_t)(px * SAB + (ci0 + j * 8) * 2);
            *(uint4*)(Ah + off) = make_uint4(hp[0], hp[1], hp[2], hp[3]);
            *(uint4*)(Al + off) = make_uint4(lp[0], lp[1], lp[2], lp[3]);
        }
        __syncthreads();   // A ready

        if (t < 8) load_tap(t + 1);   // prefetch next tap (overlaps MMAs)

        // --- compute tap t
        const char* Bh0 = Bw + (t * 2 + 0) * 64 * SAB;
        const char* Bl0 = Bw + (t * 2 + 1) * 64 * SAB;
        const int brow = (wn * 32 + (lane >> 2)) * SAB + (lane & 3) * 4;

#pragma unroll
        for (int ks = 0; ks < KSTEPS; ++ks) {
            uint32_t a_h[2][4], a_l[2][4];
#pragma unroll
            for (int mf = 0; mf < 2; ++mf) {
                uint32_t off = (uint32_t)((wm * 32 + mf * 16 + (lane & 15)) * SAB
                                          + ks * 32 + (lane >> 4) * 16);
                ldmA(a_h[mf], AhU + off);
                ldmA(a_l[mf], AlU + off);
            }
            uint32_t b_h[4][2], b_l[4][2];
#pragma unroll
            for (int nf = 0; nf < 4; ++nf) {
                const char* ph = Bh0 + brow + nf * 8 * SAB + ks * 32;
                const char* pl = Bl0 + brow + nf * 8 * SAB + ks * 32;
                b_h[nf][0] = *(const uint32_t*)ph;
                b_h[nf][1] = *(const uint32_t*)(ph + 16);
                b_l[nf][0] = *(const uint32_t*)pl;
                b_l[nf][1] = *(const uint32_t*)(pl + 16);
            }
#pragma unroll
            for (int mf = 0; mf < 2; ++mf)
#pragma unroll
                for (int nf = 0; nf < 4; ++nf) {
                    mma16816(acc[mf][nf], a_h[mf], b_h[nf]);
                    mma16816(acc[mf][nf], a_h[mf], b_l[nf]);
                    mma16816(acc[mf][nf], a_l[mf], b_h[nf]);
                }
        }
    }

    // --- epilogue: bias + relu, NHWC store
    const int prow = lane >> 2;
    const int cbase = wn * 32 + 2 * (lane & 3);
#pragma unroll
    for (int mf = 0; mf < 2; ++mf) {
#pragma unroll
        for (int nf = 0; nf < 4; ++nf) {
            int co = cbase + nf * 8;
            float b0 = bias_s[co], b1 = bias_s[co + 1];
            int p0 = x0 + wm * 32 + mf * 16 + prow;
            float* o0 = out + (((size_t)bz * HW + y) * HW + p0) * 64 + co;
            float2 v;
            v.x = fmaxf(acc[mf][nf][0] + b0, 0.f);
            v.y = fmaxf(acc[mf][nf][1] + b1, 0.f);
            *(float2*)o0 = v;
            float* o1 = o0 + 8 * 64;
            v.x = fmaxf(acc[mf][nf][2] + b0, 0.f);
            v.y = fmaxf(acc[mf][nf][3] + b1, 0.f);
            *(float2*)o1 = v;
        }
    }
}

// ---------------------------------------------------------------------------
// Head: GAP(f4) -> FC chain -> softmax -> pred_cls + argmax cls
// ---------------------------------------------------------------------------
__global__ void head_kernel(const float* __restrict__ f4,
                            const float* __restrict__ Wc1, const float* __restrict__ bc1,
                            const float* __restrict__ Wc2, const float* __restrict__ bc2,
                            const float* __restrict__ Wc3, const float* __restrict__ bc3,
                            float* __restrict__ out_pred)
{
    __shared__ float gap[256];
    __shared__ float z1[128];
    __shared__ float z2[128];
    __shared__ float logits[3];

    const int b = blockIdx.x;
    const int tid = threadIdx.x;

    const float* p = f4 + (size_t)b * 1024 * 256 + tid;
    float s0 = 0.f, s1 = 0.f, s2 = 0.f, s3 = 0.f;
    for (int i = 0; i < 1024; i += 4) {
        s0 += p[(i + 0) * 256];
        s1 += p[(i + 1) * 256];
        s2 += p[(i + 2) * 256];
        s3 += p[(i + 3) * 256];
    }
    gap[tid] = (s0 + s1 + s2 + s3) * (1.0f / 1024.0f);
    __syncthreads();

    if (tid < 128) {
        float a = bc1[tid];
#pragma unroll 8
        for (int k = 0; k < 256; ++k) a = fmaf(gap[k], Wc1[k * 128 + tid], a);
        z1[tid] = fmaxf(a, 0.f);
    }
    __syncthreads();

    if (tid < 128) {
        float a = bc2[tid];
#pragma unroll 8
        for (int k = 0; k < 128; ++k) a = fmaf(z1[k], Wc2[k * 128 + tid], a);
        z2[tid] = fmaxf(a, 0.f);
    }
    __syncthreads();

    if (tid < 3) {
        float a = bc3[tid];
        for (int k = 0; k < 128; ++k) a = fmaf(z2[k], Wc3[k * 3 + tid], a);
        logits[tid] = a;
    }
    __syncthreads();

    if (tid == 0) {
        float l0 = logits[0], l1 = logits[1], l2 = logits[2];
        float m = fmaxf(l0, fmaxf(l1, l2));
        float e0 = expf(l0 - m), e1 = expf(l1 - m), e2 = expf(l2 - m);
        float inv = 1.f / (e0 + e1 + e2);
        out_pred[b * 3 + 0] = e0 * inv;
        out_pred[b * 3 + 1] = e1 * inv;
        out_pred[b * 3 + 2] = e2 * inv;
        int c = 0; float best = l0;
        if (l1 > best) { best = l1; c = 1; }
        if (l2 > best) { best = l2; c = 2; }
        g_cls[b] = c;
    }
}

// ---------------------------------------------------------------------------
// Final convs fused with channel gather (only selected channels computed).
// ---------------------------------------------------------------------------
__global__ void __launch_bounds__(256, 1)
conv3_select(const float* __restrict__ h2o, const float* __restrict__ h2w,
             const float* __restrict__ Wo3, const float* __restrict__ bo3,
             const float* __restrict__ Ww3, const float* __restrict__ bw3,
             float* __restrict__ out)
{
    extern __shared__ float smem[];
    float* ho = smem;                 // 64 * 342  (ci-major, pitch 19)
    float* hw = smem + 64 * 342;
    float* ws = smem + 2 * 64 * 342;  // 576 * 3 selected weights

    const int b   = blockIdx.z;
    const int y0  = blockIdx.y * 16;
    const int x0  = blockIdx.x * 16;
    const int tid = threadIdx.x;
    const int cls = g_cls[b];

    for (int i = tid; i < 576; i += 256) {
        ws[i * 3 + 0] = Wo3[i * 6 + 2 * cls];
        ws[i * 3 + 1] = Wo3[i * 6 + 2 * cls + 1];
        ws[i * 3 + 2] = Ww3[i * 3 + cls];
    }

    const float* po = h2o + (size_t)b * HW * HW * 64;
    const float* pw = h2w + (size_t)b * HW * HW * 64;
    for (int i = tid; i < 324 * 16; i += 256) {
        int ci4 = i & 15;
        int rc  = i >> 4;
        int r = rc / 18, c = rc % 18;
        int gy = y0 + r - 1, gx = x0 + c - 1;
        float4 vo = make_float4(0.f, 0.f, 0.f, 0.f);
        float4 vw = vo;
        if ((unsigned)gy < HW && (unsigned)gx < HW) {
            size_t g = ((size_t)gy * HW + gx) * 64 + ci4 * 4;
            vo = *(const float4*)&po[g];
            vw = *(const float4*)&pw[g];
        }
        int base = r * 19 + c;
        ho[(ci4 * 4 + 0) * 342 + base] = vo.x;
        ho[(ci4 * 4 + 1) * 342 + base] = vo.y;
        ho[(ci4 * 4 + 2) * 342 + base] = vo.z;
        ho[(ci4 * 4 + 3) * 342 + base] = vo.w;
        hw[(ci4 * 4 + 0) * 342 + base] = vw.x;
        hw[(ci4 * 4 + 1) * 342 + base] = vw.y;
        hw[(ci4 * 4 + 2) * 342 + base] = vw.z;
        hw[(ci4 * 4 + 3) * 342 + base] = vw.w;
    }
    __syncthreads();

    const int r = tid >> 4, c = tid & 15;
    float o0 = bo3[2 * cls], o1 = bo3[2 * cls + 1], wv = bw3[cls];

#pragma unroll 1
    for (int ky = 0; ky < 3; ++ky) {
#pragma unroll 1
        for (int kx = 0; kx < 3; ++kx) {
            int base = (r + ky) * 19 + (c + kx);
            const float* wp = &ws[(ky * 3 + kx) * 64 * 3];
#pragma unroll 8
            for (int ci = 0; ci < 64; ++ci) {
                float ao = ho[ci * 342 + base];
                float aw = hw[ci * 342 + base];
                o0 = fmaf(ao, wp[ci * 3 + 0], o0);
                o1 = fmaf(ao, wp[ci * 3 + 1], o1);
                wv = fmaf(aw, wp[ci * 3 + 2], wv);
            }
        }
    }

    int gy = y0 + r, gx = x0 + c;
    size_t pix = ((size_t)b * HW + gy) * HW + gx;
    *(float2*)&out[pix * 2] = make_float2(o0, o1);
    out[(size_t)BATCH * HW * HW * 2 + pix] = wv;
}

// ---------------------------------------------------------------------------
extern "C" void kernel_launch(void* const* d_in, const int* in_sizes, int n_in,
                              void* d_out, int out_size)
{
    (void)in_sizes; (void)n_in; (void)out_size;
    const float* x0  = (const float*)d_in[0];
    const float* f4  = (const float*)d_in[1];
    const float* Wo1 = (const float*)d_in[2];
    const float* bo1 = (const float*)d_in[3];
    const float* Wo2 = (const float*)d_in[4];
    const float* bo2 = (const float*)d_in[5];
    const float* Wo3 = (const float*)d_in[6];
    const float* bo3 = (const float*)d_in[7];
    const float* Ww1 = (const float*)d_in[8];
    const float* bw1 = (const float*)d_in[9];
    const float* Ww2 = (const float*)d_in[10];
    const float* bw2 = (const float*)d_in[11];
    const float* Ww3 = (const float*)d_in[12];
    const float* bw3 = (const float*)d_in[13];
    const float* Wc1 = (const float*)d_in[14];
    const float* bc1 = (const float*)d_in[15];
    const float* Wc2 = (const float*)d_in[16];
    const float* bc2 = (const float*)d_in[17];
    const float* Wc3 = (const float*)d_in[18];
    const float* bc3 = (const float*)d_in[19];
    float* out = (float*)d_out;

    void *pA, *pB, *pC;
    cudaGetSymbolAddress(&pA, g_bufA);
    cudaGetSymbolAddress(&pB, g_bufB);
    cudaGetSymbolAddress(&pC, g_bufC);
    float* bufA = (float*)pA;
    float* bufB = (float*)pB;
    float* bufC = (float*)pC;

    // smem sizes: 256 + 2*128*SAB + 18*64*SAB
    const size_t smem32 = 256 + (size_t)(2 * 128 + 18 * 64) * (32 + 8) * 2;  // 113 KB
    const size_t smem64 = 256 + (size_t)(2 * 128 + 18 * 64) * (64 + 8) * 2;  // 203 KB
    const size_t smem3  = (size_t)(2 * 64 * 342 + 576 * 3) * sizeof(float);  // 182 KB

    cudaFuncSetAttribute(conv3x3_hmma<32>, cudaFuncAttributeMaxDynamicSharedMemorySize, (int)smem32);
    cudaFuncSetAttribute(conv3x3_hmma<64>, cudaFuncAttributeMaxDynamicSharedMemorySize, (int)smem64);
    cudaFuncSetAttribute(conv3_select,     cudaFuncAttributeMaxDynamicSharedMemorySize, (int)smem3);

    float* pred = out + (size_t)BATCH * HW * HW * 3;

    head_kernel<<<BATCH, 256>>>(f4, Wc1, bc1, Wc2, bc2, Wc3, bc3, pred);

    dim3 gmma(HW / 128, HW, BATCH);   // 4 x-tiles, 512 rows, 4 batches
    conv3x3_hmma<32><<<gmma, 256, smem32>>>(x0, Wo1, bo1, bufA);    // offsets L1
    conv3x3_hmma<32><<<gmma, 256, smem32>>>(x0, Ww1, bw1, bufB);    // weights L1
    conv3x3_hmma<64><<<gmma, 256, smem64>>>(bufA, Wo2, bo2, bufC);  // offsets L2
    conv3x3_hmma<64><<<gmma, 256, smem64>>>(bufB, Ww2, bw2, bufA);  // weights L2

    dim3 g3(HW / 16, HW / 16, BATCH);
    conv3_select<<<g3, 256, smem3>>>(bufC, bufA, Wo3, bo3, Ww3, bw3, out);
}

// round 5
// speedup vs baseline: 3.2596x; 3.2596x over previous
#include <cuda_runtime.h>
#include <cuda_bf16.h>
#include <math.h>
#include <stdint.h>

#define BATCH 4
#define HW    512
#define CMID  64

// ---------------------------------------------------------------------------
// Scratch (allocation-free rule: __device__ globals)
// ---------------------------------------------------------------------------
__device__ __align__(256) float g_bufA[(size_t)BATCH * HW * HW * CMID];
__device__ __align__(256) float g_bufB[(size_t)BATCH * HW * HW * CMID];
__device__ __align__(256) float g_bufC[(size_t)BATCH * HW * HW * CMID];
__device__ __align__(256) __nv_bfloat16 g_wprep[9 * 2 * 64 * 64];  // [tap][split][co][ci]
__device__ int g_cls[BATCH];

__device__ __forceinline__ uint32_t smem_u32(const void* p) {
    uint32_t a;
    asm("{ .reg .u64 t; cvta.to.shared.u64 t, %1; cvt.u32.u64 %0, t; }"
        : "=r"(a) : "l"(p));
    return a;
}
__device__ __forceinline__ void ldm_x4(uint32_t* r, uint32_t addr) {
    asm volatile("ldmatrix.sync.aligned.m8n8.x4.shared.b16 {%0,%1,%2,%3}, [%4];"
                 : "=r"(r[0]), "=r"(r[1]), "=r"(r[2]), "=r"(r[3]) : "r"(addr));
}
__device__ __forceinline__ void mma16816(float* d, const uint32_t* a, const uint32_t* b) {
    asm volatile(
        "mma.sync.aligned.m16n8k16.row.col.f32.bf16.bf16.f32 "
        "{%0,%1,%2,%3}, {%4,%5,%6,%7}, {%8,%9}, {%0,%1,%2,%3};"
        : "+f"(d[0]), "+f"(d[1]), "+f"(d[2]), "+f"(d[3])
        : "r"(a[0]), "r"(a[1]), "r"(a[2]), "r"(a[3]), "r"(b[0]), "r"(b[1]));
}

// ---------------------------------------------------------------------------
// Weight prep: HWIO fp32 w[(tap*CIN+ci)*64+co] ->
//   g_wprep[((tap*2+split)*64+co)*CIN+ci]  (bf16 hi/lo split)
// ---------------------------------------------------------------------------
__global__ void prep_weights(const float* __restrict__ w, __nv_bfloat16* __restrict__ wp,
                             int CIN)
{
    int total = 9 * CIN * 64;
    for (int i = blockIdx.x * 256 + threadIdx.x; i < total; i += gridDim.x * 256) {
        int co  = i % 64;
        int ci  = (i / 64) % CIN;
        int tap = i / (64 * CIN);
        float f = w[i];
        __nv_bfloat16 h = __float2bfloat16(f);
        __nv_bfloat16 l = __float2bfloat16(f - __bfloat162float(h));
        wp[((size_t)(tap * 2 + 0) * 64 + co) * CIN + ci] = h;
        wp[((size_t)(tap * 2 + 1) * 64 + co) * CIN + ci] = l;
    }
}

// ---------------------------------------------------------------------------
// 3x3 SAME conv, CIN -> 64, ReLU, mma.sync bf16x3.
// Block: 128 consecutive pixels of one row x 64 co. 8 warps = 4(M) x 2(N).
// Per ky: stage one 130-px A strip (hi/lo) + 3 taps of prepped B, then all
// 3 kx taps of MMAs read the same strip at row offset +kx.
// ---------------------------------------------------------------------------
template <int CIN>
__global__ void __launch_bounds__(256, 2)
conv3x3_hmma(const float* __restrict__ in, const __nv_bfloat16* __restrict__ wp,
             const float* __restrict__ bias, float* __restrict__ out)
{
    constexpr int SAB    = CIN * 2 + 16;   // bytes per A strip row (pad 16B)
    constexpr int SBB    = CIN * 2 + 16;   // bytes per B row
    constexpr int KSTEPS = CIN / 16;

    extern __shared__ char sm[];
    float* bias_s = (float*)sm;                        // 256 B
    char*  Ah = sm + 256;                              // 130 * SAB
    char*  Al = Ah + 130 * SAB;                        // 130 * SAB
    char*  Bs = Al + 130 * SAB;                        // 6 * 64 * SBB

    const int tid  = threadIdx.x;
    const int lane = tid & 31;
    const int wid  = tid >> 5;
    const int wm   = wid >> 1;        // 0..3
    const int wn   = wid & 1;         // 0..1
    const int x0   = blockIdx.x * 128;
    const int y    = blockIdx.y;
    const int bz   = blockIdx.z;

    if (tid < 64) bias_s[tid] = bias[tid];

    float acc[2][4][4];
#pragma unroll
    for (int mf = 0; mf < 2; ++mf)
#pragma unroll
        for (int nf = 0; nf < 4; ++nf)
#pragma unroll
            for (int q = 0; q < 4; ++q) acc[mf][nf][q] = 0.f;

    const uint32_t AhU = smem_u32(Ah);
    const uint32_t AlU = smem_u32(Al);
    const uint32_t BsU = smem_u32(Bs);

    for (int ky = 0; ky < 3; ++ky) {
        __syncthreads();   // previous ky's consumers done

        // --- stage B: 3 taps x 2 splits x 64 rows, vectorized uint4 copies
        {
            constexpr int V  = CIN / 8;            // uint4 per row
            constexpr int NV = 6 * 64 * V;
            for (int i = tid; i < NV; i += 256) {
                int c   = i % V;
                int row = (i / V) % 64;
                int lt  = i / (V * 64);            // 0..5 = kx*2+split
                int split = lt & 1, kx = lt >> 1;
                uint4 v = *(const uint4*)&wp[((size_t)((ky * 3 + kx) * 2 + split) * 64 + row) * CIN + c * 8];
                *(uint4*)(Bs + ((lt * 64) + row) * SBB + c * 16) = v;
            }
        }

        // --- stage A strip: 130 px (gx = x0-1 .. x0+128) of row y+ky-1
        {
            const int gy = y + ky - 1;
            const bool rowok = (unsigned)gy < HW;
            const float* src = in + (((size_t)bz * HW + gy) * HW) * CIN;
            for (int i = tid; i < 130 * (CIN / 4); i += 256) {
                int ci4 = i % (CIN / 4);
                int r   = i / (CIN / 4);
                int gx  = x0 - 1 + r;
                float4 v = make_float4(0.f, 0.f, 0.f, 0.f);
                if (rowok && (unsigned)gx < HW)
                    v = *(const float4*)&src[(size_t)gx * CIN + ci4 * 4];
                __nv_bfloat162 h0 = __float22bfloat162_rn(make_float2(v.x, v.y));
                __nv_bfloat162 h1 = __float22bfloat162_rn(make_float2(v.z, v.w));
                __nv_bfloat162 l0 = __float22bfloat162_rn(make_float2(
                    v.x - __bfloat162float(h0.x), v.y - __bfloat162float(h0.y)));
                __nv_bfloat162 l1 = __float22bfloat162_rn(make_float2(
                    v.z - __bfloat162float(h1.x), v.w - __bfloat162float(h1.y)));
                *(uint2*)(Ah + r * SAB + ci4 * 8) =
                    make_uint2(*(uint32_t*)&h0, *(uint32_t*)&h1);
                *(uint2*)(Al + r * SAB + ci4 * 8) =
                    make_uint2(*(uint32_t*)&l0, *(uint32_t*)&l1);
            }
        }
        __syncthreads();   // strip + B ready

        // --- compute 3 kx taps off the same strip
        // ldmatrix lane addressing
        const int arow_base = wm * 32 + (lane & 15);
        const int acol      = (lane >> 4) * 16;
        const int brow_in   = (lane & 7) + ((lane >> 4) & 1) * 8;  // within 16-n group
        const int bcol      = ((lane >> 3) & 1) * 16;

#pragma unroll
        for (int kx = 0; kx < 3; ++kx) {
            const uint32_t Bh = BsU + ((kx * 2 + 0) * 64) * SBB;
            const uint32_t Bl = BsU + ((kx * 2 + 1) * 64) * SBB;
#pragma unroll
            for (int ks = 0; ks < KSTEPS; ++ks) {
                uint32_t a_h[2][4], a_l[2][4];
#pragma unroll
                for (int mf = 0; mf < 2; ++mf) {
                    uint32_t off = (uint32_t)((arow_base + mf * 16 + kx) * SAB + ks * 32 + acol);
                    ldm_x4(a_h[mf], AhU + off);
                    ldm_x4(a_l[mf], AlU + off);
                }
                uint32_t b_h[2][4], b_l[2][4];   // [nhalf][4 regs: nf even{0,1}, nf odd{2,3}]
#pragma unroll
                for (int nh = 0; nh < 2; ++nh) {
                    uint32_t roff = (uint32_t)((wn * 32 + nh * 16 + brow_in) * SBB + ks * 32 + bcol);
                    ldm_x4(b_h[nh], Bh + roff);
                    ldm_x4(b_l[nh], Bl + roff);
                }
#pragma unroll
                for (int mf = 0; mf < 2; ++mf)
#pragma unroll
                    for (int nf = 0; nf < 4; ++nf) {
                        const uint32_t* bh = &b_h[nf >> 1][(nf & 1) * 2];
                        const uint32_t* bl = &b_l[nf >> 1][(nf & 1) * 2];
                        mma16816(acc[mf][nf], a_h[mf], bh);
                        mma16816(acc[mf][nf], a_h[mf], bl);
                        mma16816(acc[mf][nf], a_l[mf], bh);
                    }
            }
        }
    }

    // --- epilogue: bias + relu, NHWC store
    const int prow  = lane >> 2;
    const int cbase = wn * 32 + 2 * (lane & 3);
#pragma unroll
    for (int mf = 0; mf < 2; ++mf) {
#pragma unroll
        for (int nf = 0; nf < 4; ++nf) {
            int co = cbase + nf * 8;
            float b0 = bias_s[co], b1 = bias_s[co + 1];
            int p0 = x0 + wm * 32 + mf * 16 + prow;
            float* o0 = out + (((size_t)bz * HW + y) * HW + p0) * 64 + co;
            float2 v;
            v.x = fmaxf(acc[mf][nf][0] + b0, 0.f);
            v.y = fmaxf(acc[mf][nf][1] + b1, 0.f);
            *(float2*)o0 = v;
            float* o1 = o0 + 8 * 64;
            v.x = fmaxf(acc[mf][nf][2] + b0, 0.f);
            v.y = fmaxf(acc[mf][nf][3] + b1, 0.f);
            *(float2*)o1 = v;
        }
    }
}

// ---------------------------------------------------------------------------
// Head: GAP(f4) -> FC chain -> softmax -> pred_cls + argmax cls
// ---------------------------------------------------------------------------
__global__ void head_kernel(const float* __restrict__ f4,
                            const float* __restrict__ Wc1, const float* __restrict__ bc1,
                            const float* __restrict__ Wc2, const float* __restrict__ bc2,
                            const float* __restrict__ Wc3, const float* __restrict__ bc3,
                            float* __restrict__ out_pred)
{
    __shared__ float gap[256];
    __shared__ float z1[128];
    __shared__ float z2[128];
    __shared__ float logits[3];

    const int b = blockIdx.x;
    const int tid = threadIdx.x;

    const float* p = f4 + (size_t)b * 1024 * 256 + tid;
    float s0 = 0.f, s1 = 0.f, s2 = 0.f, s3 = 0.f;
    for (int i = 0; i < 1024; i += 4) {
        s0 += p[(i + 0) * 256];
        s1 += p[(i + 1) * 256];
        s2 += p[(i + 2) * 256];
        s3 += p[(i + 3) * 256];
    }
    gap[tid] = (s0 + s1 + s2 + s3) * (1.0f / 1024.0f);
    __syncthreads();

    if (tid < 128) {
        float a = bc1[tid];
#pragma unroll 8
        for (int k = 0; k < 256; ++k) a = fmaf(gap[k], Wc1[k * 128 + tid], a);
        z1[tid] = fmaxf(a, 0.f);
    }
    __syncthreads();

    if (tid < 128) {
        float a = bc2[tid];
#pragma unroll 8
        for (int k = 0; k < 128; ++k) a = fmaf(z1[k], Wc2[k * 128 + tid], a);
        z2[tid] = fmaxf(a, 0.f);
    }
    __syncthreads();

    if (tid < 3) {
        float a = bc3[tid];
        for (int k = 0; k < 128; ++k) a = fmaf(z2[k], Wc3[k * 3 + tid], a);
        logits[tid] = a;
    }
    __syncthreads();

    if (tid == 0) {
        float l0 = logits[0], l1 = logits[1], l2 = logits[2];
        float m = fmaxf(l0, fmaxf(l1, l2));
        float e0 = expf(l0 - m), e1 = expf(l1 - m), e2 = expf(l2 - m);
        float inv = 1.f / (e0 + e1 + e2);
        out_pred[b * 3 + 0] = e0 * inv;
        out_pred[b * 3 + 1] = e1 * inv;
        out_pred[b * 3 + 2] = e2 * inv;
        int c = 0; float best = l0;
        if (l1 > best) { best = l1; c = 1; }
        if (l2 > best) { best = l2; c = 2; }
        g_cls[b] = c;
    }
}

// ---------------------------------------------------------------------------
// Final convs fused with channel gather (only selected channels computed).
// ---------------------------------------------------------------------------
__global__ void __launch_bounds__(256, 1)
conv3_select(const float* __restrict__ h2o, const float* __restrict__ h2w,
             const float* __restrict__ Wo3, const float* __restrict__ bo3,
             const float* __restrict__ Ww3, const float* __restrict__ bw3,
             float* __restrict__ out)
{
    extern __shared__ float smem[];
    float* ho = smem;                 // 64 * 342  (ci-major, pitch 19)
    float* hw = smem + 64 * 342;
    float* ws = smem + 2 * 64 * 342;  // 576 * 3 selected weights

    const int b   = blockIdx.z;
    const int y0  = blockIdx.y * 16;
    const int x0  = blockIdx.x * 16;
    const int tid = threadIdx.x;
    const int cls = g_cls[b];

    for (int i = tid; i < 576; i += 256) {
        ws[i * 3 + 0] = Wo3[i * 6 + 2 * cls];
        ws[i * 3 + 1] = Wo3[i * 6 + 2 * cls + 1];
        ws[i * 3 + 2] = Ww3[i * 3 + cls];
    }

    const float* po = h2o + (size_t)b * HW * HW * 64;
    const float* pw = h2w + (size_t)b * HW * HW * 64;
    for (int i = tid; i < 324 * 16; i += 256) {
        int ci4 = i & 15;
        int rc  = i >> 4;
        int r = rc / 18, c = rc % 18;
        int gy = y0 + r - 1, gx = x0 + c - 1;
        float4 vo = make_float4(0.f, 0.f, 0.f, 0.f);
        float4 vw = vo;
        if ((unsigned)gy < HW && (unsigned)gx < HW) {
            size_t g = ((size_t)gy * HW + gx) * 64 + ci4 * 4;
            vo = *(const float4*)&po[g];
            vw = *(const float4*)&pw[g];
        }
        int base = r * 19 + c;
        ho[(ci4 * 4 + 0) * 342 + base] = vo.x;
        ho[(ci4 * 4 + 1) * 342 + base] = vo.y;
        ho[(ci4 * 4 + 2) * 342 + base] = vo.z;
        ho[(ci4 * 4 + 3) * 342 + base] = vo.w;
        hw[(ci4 * 4 + 0) * 342 + base] = vw.x;
        hw[(ci4 * 4 + 1) * 342 + base] = vw.y;
        hw[(ci4 * 4 + 2) * 342 + base] = vw.z;
        hw[(ci4 * 4 + 3) * 342 + base] = vw.w;
    }
    __syncthreads();

    const int r = tid >> 4, c = tid & 15;
    float o0 = bo3[2 * cls], o1 = bo3[2 * cls + 1], wv = bw3[cls];

#pragma unroll 1
    for (int ky = 0; ky < 3; ++ky) {
#pragma unroll 1
        for (int kx = 0; kx < 3; ++kx) {
            int base = (r + ky) * 19 + (c + kx);
            const float* wp = &ws[(ky * 3 + kx) * 64 * 3];
#pragma unroll 8
            for (int ci = 0; ci < 64; ++ci) {
                float ao = ho[ci * 342 + base];
                float aw = hw[ci * 342 + base];
                o0 = fmaf(ao, wp[ci * 3 + 0], o0);
                o1 = fmaf(ao, wp[ci * 3 + 1], o1);
                wv = fmaf(aw, wp[ci * 3 + 2], wv);
            }
        }
    }

    int gy = y0 + r, gx = x0 + c;
    size_t pix = ((size_t)b * HW + gy) * HW + gx;
    *(float2*)&out[pix * 2] = make_float2(o0, o1);
    out[(size_t)BATCH * HW * HW * 2 + pix] = wv;
}

// ---------------------------------------------------------------------------
extern "C" void kernel_launch(void* const* d_in, const int* in_sizes, int n_in,
                              void* d_out, int out_size)
{
    (void)in_sizes; (void)n_in; (void)out_size;
    const float* x0  = (const float*)d_in[0];
    const float* f4  = (const float*)d_in[1];
    const float* Wo1 = (const float*)d_in[2];
    const float* bo1 = (const float*)d_in[3];
    const float* Wo2 = (const float*)d_in[4];
    const float* bo2 = (const float*)d_in[5];
    const float* Wo3 = (const float*)d_in[6];
    const float* bo3 = (const float*)d_in[7];
    const float* Ww1 = (const float*)d_in[8];
    const float* bw1 = (const float*)d_in[9];
    const float* Ww2 = (const float*)d_in[10];
    const float* bw2 = (const float*)d_in[11];
    const float* Ww3 = (const float*)d_in[12];
    const float* bw3 = (const float*)d_in[13];
    const float* Wc1 = (const float*)d_in[14];
    const float* bc1 = (const float*)d_in[15];
    const float* Wc2 = (const float*)d_in[16];
    const float* bc2 = (const float*)d_in[17];
    const float* Wc3 = (const float*)d_in[18];
    const float* bc3 = (const float*)d_in[19];
    float* out = (float*)d_out;

    void *pA, *pB, *pC, *pW;
    cudaGetSymbolAddress(&pA, g_bufA);
    cudaGetSymbolAddress(&pB, g_bufB);
    cudaGetSymbolAddress(&pC, g_bufC);
    cudaGetSymbolAddress(&pW, g_wprep);
    float* bufA = (float*)pA;
    float* bufB = (float*)pB;
    float* bufC = (float*)pC;
    __nv_bfloat16* wprep = (__nv_bfloat16*)pW;

    // smem: 256 + 2*130*SAB + 6*64*SBB
    const size_t smem32 = 256 + (size_t)(2 * 130 + 6 * 64) * (32 * 2 + 16);  //  51.8 KB
    const size_t smem64 = 256 + (size_t)(2 * 130 + 6 * 64) * (64 * 2 + 16);  //  93.0 KB
    const size_t smem3  = (size_t)(2 * 64 * 342 + 576 * 3) * sizeof(float);  // 182.0 KB

    cudaFuncSetAttribute(conv3x3_hmma<32>, cudaFuncAttributeMaxDynamicSharedMemorySize, (int)smem32);
    cudaFuncSetAttribute(conv3x3_hmma<64>, cudaFuncAttributeMaxDynamicSharedMemorySize, (int)smem64);
    cudaFuncSetAttribute(conv3_select,     cudaFuncAttributeMaxDynamicSharedMemorySize, (int)smem3);

    float* pred = out + (size_t)BATCH * HW * HW * 3;

    head_kernel<<<BATCH, 256>>>(f4, Wc1, bc1, Wc2, bc2, Wc3, bc3, pred);

    dim3 gmma(HW / 128, HW, BATCH);   // 4 x-tiles, 512 rows, 4 batches

    prep_weights<<<72, 256>>>(Wo1, wprep, 32);
    conv3x3_hmma<32><<<gmma, 256, smem32>>>(x0, wprep, bo1, bufA);    // offsets L1
    prep_weights<<<72, 256>>>(Ww1, wprep, 32);
    conv3x3_hmma<32><<<gmma, 256, smem32>>>(x0, wprep, bw1, bufB);    // weights L1
    prep_weights<<<72, 256>>>(Wo2, wprep, 64);
    conv3x3_hmma<64><<<gmma, 256, smem64>>>(bufA, wprep, bo2, bufC);  // offsets L2
    prep_weights<<<72, 256>>>(Ww2, wprep, 64);
    conv3x3_hmma<64><<<gmma, 256, smem64>>>(bufB, wprep, bw2, bufA);  // weights L2

    dim3 g3(HW / 16, HW / 16, BATCH);
    conv3_select<<<g3, 256, smem3>>>(bufC, bufA, Wo3, bo3, Ww3, bw3, out);
}